// round 4
// baseline (speedup 1.0000x reference)
#include <cuda_runtime.h>

// xin[800,100] = x[800,460800] @ w_in[100,460800]^T  (exact-ish fp32, FFMA2)
// then 50-step LIF/LI scan over 16 batch lanes -> voltages [50,16,6].
//
// GEMM: split-K=45, row-tiles of 80, H padded to 128. Packed fp32 FFMA2
// inner loop. 3-tier pairwise register accumulation to keep summation error
// ~1e-5 per split (serial chains flip spikes at the LIF threshold).

#define F_K   460800L
#define SPLITS 45
#define KSPL  10240
#define KB    16
#define TM    80
#define ROWS  800
#define HPAD  128

typedef unsigned long long ull;

// scratch (no allocation allowed)
__device__ float g_part[SPLITS * ROWS * HPAD];   // 18.4 MB
__device__ float g_xin[ROWS * 100];

__device__ __forceinline__ void fma2(ull& acc, ull a, ull b) {
    asm("fma.rn.f32x2 %0, %1, %2, %0;" : "+l"(acc) : "l"(a), "l"(b));
}
__device__ __forceinline__ void fadd2(ull& acc, ull v) {
    asm("add.rn.f32x2 %0, %0, %1;" : "+l"(acc) : "l"(v));
}

__global__ __launch_bounds__(256) void gemm_kernel(const float* __restrict__ X,
                                                   const float* __restrict__ W) {
    __shared__ __align__(16) float Xs[TM][20];    // 80 rows x 16 k (pad 20)
    __shared__ __align__(16) float Ws[KB][132];   // transposed: k-major, 128 cols (pad 132)
    const int rt = blockIdx.x, sp = blockIdx.y;
    const int tid = threadIdx.x, ty = tid >> 4, tx = tid & 15;
    const long k0 = (long)sp * KSPL;
    const float* Xb = X + (long)rt * TM * F_K + k0;
    const float* Wb = W + k0;

    ull accI[5][4], accM[5][4], accO[5][4];   // 3-tier pairwise accumulators
#pragma unroll
    for (int i = 0; i < 5; i++)
#pragma unroll
        for (int j = 0; j < 4; j++) { accI[i][j] = 0ULL; accM[i][j] = 0ULL; accO[i][j] = 0ULL; }

    for (int it = 0; it < KSPL / KB; it++) {       // 640 tiles
        const int kb = it * KB;
        // X tile: 80 rows x 16 floats = 320 float4
        for (int idx = tid; idx < TM * 4; idx += 256) {
            int r = idx >> 2, q = idx & 3;
            float4 v = *(const float4*)(Xb + (long)r * F_K + kb + q * 4);
            *(float4*)&Xs[r][q * 4] = v;
        }
        // W tile transposed; rows >= 100 are zero padding
        for (int idx = tid; idx < HPAD * 4; idx += 256) {
            int j = idx >> 2, q = idx & 3;
            float4 v = make_float4(0.f, 0.f, 0.f, 0.f);
            if (j < 100) v = *(const float4*)(Wb + (long)j * F_K + kb + q * 4);
            Ws[q * 4 + 0][j] = v.x; Ws[q * 4 + 1][j] = v.y;
            Ws[q * 4 + 2][j] = v.z; Ws[q * 4 + 3][j] = v.w;
        }
        __syncthreads();
#pragma unroll
        for (int k = 0; k < KB; k++) {
            ulonglong2 B0 = *(const ulonglong2*)&Ws[k][tx * 8];
            ulonglong2 B1 = *(const ulonglong2*)&Ws[k][tx * 8 + 4];
#pragma unroll
            for (int i = 0; i < 5; i++) {
                float a = Xs[ty * 5 + i][k];
                ull aa;
                asm("mov.b64 %0, {%1, %1};" : "=l"(aa) : "f"(a));
                fma2(accI[i][0], aa, B0.x);
                fma2(accI[i][1], aa, B0.y);
                fma2(accI[i][2], aa, B1.x);
                fma2(accI[i][3], aa, B1.y);
            }
        }
        __syncthreads();
        if ((it & 1) == 1) {                       // inner -> mid every 2 tiles
#pragma unroll
            for (int i = 0; i < 5; i++)
#pragma unroll
                for (int j = 0; j < 4; j++) { fadd2(accM[i][j], accI[i][j]); accI[i][j] = 0ULL; }
        }
        if (it % 40 == 39) {                       // mid -> outer every 40 tiles
#pragma unroll
            for (int i = 0; i < 5; i++)
#pragma unroll
                for (int j = 0; j < 4; j++) { fadd2(accO[i][j], accM[i][j]); accM[i][j] = 0ULL; }
        }
    }
    float* out = g_part + ((long)sp * ROWS + (long)rt * TM) * HPAD;
#pragma unroll
    for (int i = 0; i < 5; i++) {
        int row = ty * 5 + i;
#pragma unroll
        for (int j = 0; j < 4; j++)
            *(ull*)&out[(long)row * HPAD + tx * 8 + j * 2] = accO[i][j];
    }
}

// deterministic split-K reduce in fp64
__global__ void reduce_kernel() {
    int row = blockIdx.x, c = threadIdx.x;
    if (c >= 100) return;
    double s = 0.0;
    for (int sp = 0; sp < SPLITS; sp++)
        s += (double)g_part[((long)sp * ROWS + row) * HPAD + c];
    g_xin[row * 100 + c] = (float)s;
}

// per-batch LIF/LI scan: 16 CTAs, one per batch lane
__global__ __launch_bounds__(128) void scan_kernel(const float* __restrict__ wrec,
                                                   const float* __restrict__ wout,
                                                   float* __restrict__ out) {
    __shared__ float sw[10000];   // w_rec [100][100]
    __shared__ float so[600];     // w_out [6][100]
    __shared__ float zs[100];
    const int b = blockIdx.x, tid = threadIdx.x;
    for (int i = tid; i < 10000; i += 128) sw[i] = wrec[i];
    for (int i = tid; i < 600; i += 128) so[i] = wout[i];
    if (tid < 100) zs[tid] = 0.f;
    float v = 0.f, ii = 0.f, vo = 0.f, io = 0.f;
    __syncthreads();

    for (int t = 0; t < 50; t++) {
        float zn = 0.f, inew = 0.f, vnew = 0.f;
        if (tid < 100) {
            float rec = 0.f;                       // recurrent uses OLD z
            for (int j = 0; j < 100; j++) rec += zs[j] * sw[tid * 100 + j];
            float vd = v + 0.1f * (ii - v);        // DT*TAU_MEM_INV = 0.1
            float id = 0.9f * ii;                  // 1 - DT*TAU_SYN_INV
            zn = (vd - 0.3f > 0.f) ? 1.f : 0.f;    // heaviside(v_dec - V_TH)
            vnew = (1.f - zn) * vd;                // reset to 0
            inew = id + g_xin[(t * 16 + b) * 100 + tid] + rec;
        }
        __syncthreads();
        if (tid < 100) { zs[tid] = zn; v = vnew; ii = inew; }
        __syncthreads();
        if (tid < 6) {                             // readout + LI cell
            float y = 0.f;
            for (int h = 0; h < 100; h++) y += zs[h] * so[tid * 100 + h];
            float von = vo + 0.1f * (io - vo);     // DT*LI_TAU_MEM_INV
            io = 0.8f * io + y;                    // 1 - DT*LI_TAU_SYN_INV
            vo = von;
            out[(t * 16 + b) * 6 + tid] = von;
        }
        __syncthreads();
    }
}

extern "C" void kernel_launch(void* const* d_in, const int* in_sizes, int n_in,
                              void* d_out, int out_size) {
    const float *x = 0, *win = 0, *wrec = 0, *wout = 0;
    for (int i = 0; i < n_in; i++) {
        if (in_sizes[i] == 368640000) x = (const float*)d_in[i];
        else if (in_sizes[i] == 46080000) win = (const float*)d_in[i];
        else if (in_sizes[i] == 10000) wrec = (const float*)d_in[i];
        else if (in_sizes[i] == 600) wout = (const float*)d_in[i];
    }
    dim3 g1(ROWS / TM, SPLITS);            // (10, 45) = 450 CTAs
    gemm_kernel<<<g1, 256>>>(x, win);
    reduce_kernel<<<ROWS, 128>>>();
    scan_kernel<<<16, 128>>>(wrec, wout, (float*)d_out);
}

// round 5
// speedup vs baseline: 1.1505x; 1.1505x over previous
#include <cuda_runtime.h>

// xin[800,100] = x[800,460800] @ w_in[100,460800]^T, then 50-step LIF/LI scan.
//
// GEMM: f32x2 packed over the K dimension (both operands load natively as 8B
// k-pairs, zero transpose/dup overhead). 384 threads, thread tile 3 rows x 7
// cols (cols strided by 16 -> each B LDS.64 is one 128B wavefront).
// Split-K=37, 12 row tiles of 72 -> grid 444 = exactly 3 waves on 148 SMs.
// Precision: per-tile inner chain (16 ffma2) -> mid tier (10 adds) -> fp64
// outer tier in smem. Deterministic fp64 split-K reduce.

#define F_K   460800L
#define SPLITS 37
#define KSPL  12480
#define KB    32
#define KP    16            // k-pairs per tile
#define TM    72
#define NROWT 12
#define NCOL  112
#define NTHREADS 384

typedef unsigned long long ull;

__device__ float g_part[SPLITS * 800 * NCOL];   // 13.3 MB scratch
__device__ float g_xin[800 * 100];

__device__ __forceinline__ void fma2(ull& acc, ull a, ull b) {
    asm("fma.rn.f32x2 %0, %1, %2, %0;" : "+l"(acc) : "l"(a), "l"(b));
}
__device__ __forceinline__ void fadd2(ull& a, ull b) {
    asm("add.rn.f32x2 %0, %0, %1;" : "+l"(a) : "l"(b));
}

#define AS_SZ (KP * 96)      // A buffer: [kp][96 row-slots] (4-slot stride/ty)
#define BS_SZ (KP * NCOL)    // B buffer: [kp][112 cols]
#define SMEM_BYTES ((2 * AS_SZ + 2 * BS_SZ) * 8 + 21 * NTHREADS * 16)

extern __shared__ ull dsm[];

__global__ void __launch_bounds__(NTHREADS, 1)
gemm_kernel(const float* __restrict__ X, const float* __restrict__ W) {
    ull* As = dsm;
    ull* Bs = dsm + 2 * AS_SZ;
    double2* Os = (double2*)(dsm + 2 * AS_SZ + 2 * BS_SZ);  // fp64 outer tier

    const int rt = blockIdx.x, sp = blockIdx.y;
    const int tid = threadIdx.x, tx = tid & 15, ty = tid >> 4;  // 16 x 24
    const long k0 = (long)sp * KSPL;
    const int ntiles = (sp == SPLITS - 1) ? (460800 - (SPLITS - 1) * KSPL) / KB
                                          : KSPL / KB;          // 390 or 360
    const int row0 = rt * TM;

#pragma unroll
    for (int i = 0; i < 21; i++) Os[i * NTHREADS + tid] = make_double2(0.0, 0.0);

    // loop-invariant staging assignments (A: 1152 pairs, B: 1792 pairs)
    long aoff[3]; int aslot[3];
#pragma unroll
    for (int q = 0; q < 3; q++) {
        int p = tid + q * NTHREADS;
        int rl = p / KP, kp = p % KP;
        int row = min(row0 + rl, 799);            // clamp pad rows (masked at store)
        aoff[q] = (long)row * F_K + k0 + 2 * kp;
        aslot[q] = kp * 96 + (rl / 3) * 4 + (rl % 3);
    }
    long boff[5]; int bslot[5]; bool bv[5];
#pragma unroll
    for (int q = 0; q < 5; q++) {
        int p = tid + q * NTHREADS;
        int col = p / KP, kp = p % KP;
        bv[q] = (p < BS_SZ) && (col < 100);       // cols 100..111 = zero pad
        boff[q] = (long)min(col, 99) * F_K + k0 + 2 * kp;
        bslot[q] = kp * NCOL + col;
    }

    ull accI[3][7], accM[3][7];
#pragma unroll
    for (int i = 0; i < 3; i++)
#pragma unroll
        for (int j = 0; j < 7; j++) { accI[i][j] = 0ULL; accM[i][j] = 0ULL; }

    ull ra[3], rb[5];
    // prologue: stage tile 0
#pragma unroll
    for (int q = 0; q < 3; q++) ra[q] = *(const ull*)(X + aoff[q]);
#pragma unroll
    for (int q = 0; q < 5; q++) rb[q] = bv[q] ? *(const ull*)(W + boff[q]) : 0ULL;
#pragma unroll
    for (int q = 0; q < 3; q++) As[aslot[q]] = ra[q];
#pragma unroll
    for (int q = 0; q < 5; q++) if (tid + q * NTHREADS < BS_SZ) Bs[bslot[q]] = rb[q];
    __syncthreads();

    for (int it = 0; it < ntiles; it++) {
        const int cur = it & 1;
        if (it + 1 < ntiles) {                    // prefetch next tile into regs
            const long kb = (long)(it + 1) * KB;
#pragma unroll
            for (int q = 0; q < 3; q++) ra[q] = *(const ull*)(X + aoff[q] + kb);
#pragma unroll
            for (int q = 0; q < 5; q++) rb[q] = bv[q] ? *(const ull*)(W + boff[q] + kb) : 0ULL;
        }
        const ull* A = As + cur * AS_SZ + 4 * ty;
        const ull* B = Bs + cur * BS_SZ + tx;
#pragma unroll
        for (int kp = 0; kp < KP; kp++) {
            ulonglong2 a01 = *(const ulonglong2*)&A[kp * 96];   // rows 3ty,3ty+1
            ull a2 = A[kp * 96 + 2];                            // row 3ty+2
#pragma unroll
            for (int j = 0; j < 7; j++) {
                ull b = B[kp * NCOL + 16 * j];                  // col tx+16j
                fma2(accI[0][j], a01.x, b);
                fma2(accI[1][j], a01.y, b);
                fma2(accI[2][j], a2, b);
            }
        }
#pragma unroll
        for (int i = 0; i < 3; i++)                // inner -> mid (pairwise)
#pragma unroll
            for (int j = 0; j < 7; j++) { fadd2(accM[i][j], accI[i][j]); accI[i][j] = 0ULL; }
        if ((it % 10) == 9) {                      // mid -> fp64 outer (smem)
#pragma unroll
            for (int i = 0; i < 3; i++)
#pragma unroll
                for (int j = 0; j < 7; j++) {
                    int id = (i * 7 + j) * NTHREADS + tid;
                    double2 o = Os[id];
                    float2 f = *(float2*)&accM[i][j];
                    o.x += (double)f.x; o.y += (double)f.y;
                    Os[id] = o;
                    accM[i][j] = 0ULL;
                }
        }
        if (it + 1 < ntiles) {                     // commit prefetched tile
            const int nxt = 1 - cur;
#pragma unroll
            for (int q = 0; q < 3; q++) As[nxt * AS_SZ + aslot[q]] = ra[q];
#pragma unroll
            for (int q = 0; q < 5; q++)
                if (tid + q * NTHREADS < BS_SZ) Bs[nxt * BS_SZ + bslot[q]] = rb[q];
        }
        __syncthreads();
    }

    // epilogue: combine even/odd k lanes, store partials (ntiles % 10 == 0 ->
    // all mid tiers already flushed to Os)
#pragma unroll
    for (int i = 0; i < 3; i++) {
        int r = row0 + ty * 3 + i;
        if (r < 800) {
#pragma unroll
            for (int j = 0; j < 7; j++) {
                double2 o = Os[(i * 7 + j) * NTHREADS + tid];
                g_part[((long)sp * 800 + r) * NCOL + tx + 16 * j] = (float)(o.x + o.y);
            }
        }
    }
}

// deterministic split-K reduce in fp64
__global__ void reduce_kernel() {
    int row = blockIdx.x, c = threadIdx.x;
    if (c >= 100) return;
    double s = 0.0;
    for (int sp = 0; sp < SPLITS; sp++)
        s += (double)g_part[((long)sp * 800 + row) * NCOL + c];
    g_xin[row * 100 + c] = (float)s;
}

// per-batch LIF/LI scan: 16 CTAs, one per batch lane (proven in R4)
__global__ __launch_bounds__(128) void scan_kernel(const float* __restrict__ wrec,
                                                   const float* __restrict__ wout,
                                                   float* __restrict__ out) {
    __shared__ float sw[10000];
    __shared__ float so[600];
    __shared__ float zs[100];
    const int b = blockIdx.x, tid = threadIdx.x;
    for (int i = tid; i < 10000; i += 128) sw[i] = wrec[i];
    for (int i = tid; i < 600; i += 128) so[i] = wout[i];
    if (tid < 100) zs[tid] = 0.f;
    float v = 0.f, ii = 0.f, vo = 0.f, io = 0.f;
    __syncthreads();

    for (int t = 0; t < 50; t++) {
        float zn = 0.f, inew = 0.f, vnew = 0.f;
        if (tid < 100) {
            float rec = 0.f;                       // recurrent uses OLD z
            for (int j = 0; j < 100; j++) rec += zs[j] * sw[tid * 100 + j];
            float vd = v + 0.1f * (ii - v);
            float id = 0.9f * ii;
            zn = (vd - 0.3f > 0.f) ? 1.f : 0.f;
            vnew = (1.f - zn) * vd;
            inew = id + g_xin[(t * 16 + b) * 100 + tid] + rec;
        }
        __syncthreads();
        if (tid < 100) { zs[tid] = zn; v = vnew; ii = inew; }
        __syncthreads();
        if (tid < 6) {
            float y = 0.f;
            for (int h = 0; h < 100; h++) y += zs[h] * so[tid * 100 + h];
            float von = vo + 0.1f * (io - vo);
            io = 0.8f * io + y;
            vo = von;
            out[(t * 16 + b) * 6 + tid] = von;
        }
        __syncthreads();
    }
}

extern "C" void kernel_launch(void* const* d_in, const int* in_sizes, int n_in,
                              void* d_out, int out_size) {
    const float *x = 0, *win = 0, *wrec = 0, *wout = 0;
    for (int i = 0; i < n_in; i++) {
        if (in_sizes[i] == 368640000) x = (const float*)d_in[i];
        else if (in_sizes[i] == 46080000) win = (const float*)d_in[i];
        else if (in_sizes[i] == 10000) wrec = (const float*)d_in[i];
        else if (in_sizes[i] == 600) wout = (const float*)d_in[i];
    }
    static int smem_set = 0;
    if (!smem_set) {
        cudaFuncSetAttribute(gemm_kernel, cudaFuncAttributeMaxDynamicSharedMemorySize,
                             SMEM_BYTES);
        smem_set = 1;
    }
    dim3 g1(NROWT, SPLITS);                // (12, 37) = 444 CTAs = 3 full waves
    gemm_kernel<<<g1, NTHREADS, SMEM_BYTES>>>(x, win);
    reduce_kernel<<<800, 128>>>();
    scan_kernel<<<16, 128>>>(wrec, wout, (float*)d_out);
}